// round 11
// baseline (speedup 1.0000x reference)
#include <cuda_runtime.h>
#include <cuda_fp16.h>

// kendallloss: 1 - 2 * [sum_{i>j} clip(p_i-p_j)*clip(t_i-t_j)] / (N*(N-1))
//
// Pipe-BALANCED hybrid, exact per pair. Per 256x256 tile, thread owns 8 i's:
//   i-regs q=0..4  (minmax form, 3 fma + 4 alu per slot):
//     pd = clamp(p_i - p_j); td = clamp(t_i - t_j); accP += pd*td
//   i-regs q=5..7  (sat-P form, 4 fma + 2 alu per slot):
//     pd' = HADD2.SAT(0.5*p_i, 0.5-0.5*p_j) = (clip(p_i-p_j)+1)/2
//     td  = clamp(t_i - t_j)
//     accP += pd'*td ;  accT += td         (clip_p*td = 2*pd'*td - td)
// Mix 5:3 -> avg 3.375 fma / 3.25 alu per slot (was 3/4, alu-bound at 4).
//
// Triangle tiling: off-diag tiles weight 2 (q symmetric), diag weight 1.
// Single kernel; last block (atomic ticket) does the double reduction.

#define MAXN 32768
#define TILE 256
#define RI   8
#define NSAT 3          /* q >= RI-NSAT use sat-P form */

__device__ double       g_part[(MAXN / TILE) * (MAXN / TILE + 1) / 2];
__device__ unsigned int g_done = 0;

__global__ __launch_bounds__(256, 7) void pair_kernel(const float* __restrict__ p,
                                                      const float* __restrict__ tg,
                                                      float* __restrict__ out,
                                                      int n, int nblocks) {
    const int b = blockIdx.x;
    // Decode lower-triangle tile index: b -> (bi, bj), bj <= bi.
    int r = (int)((sqrtf(8.0f * (float)b + 1.0f) - 1.0f) * 0.5f);
    while ((r + 1) * (r + 2) / 2 <= b) r++;
    while (r * (r + 1) / 2 > b) r--;
    const int bi = r;
    const int bj = b - r * (r + 1) / 2;

    const int t = threadIdx.x;
    const int ibase = bi * TILE;
    const int jbase = bj * TILE;

    // Stage j-side: {-p_j, -t_j} pairs and {0.5 - 0.5*p_j} for the sat path.
    __shared__ uint2    sjA[TILE / 2];
    __shared__ unsigned sjB[TILE / 2];
    if (t < TILE / 2) {
        float2 pv = *(const float2*)(p  + jbase + 2 * t);
        float2 tv = *(const float2*)(tg + jbase + 2 * t);
        __half2 np = __floats2half2_rn(-pv.x, -pv.y);
        __half2 nt = __floats2half2_rn(-tv.x, -tv.y);
        __half2 bp = __floats2half2_rn(0.5f - 0.5f * pv.x, 0.5f - 0.5f * pv.y);
        uint2 u;
        u.x = *(unsigned int*)&np;
        u.y = *(unsigned int*)&nt;
        sjA[t] = u;
        sjB[t] = *(unsigned int*)&bp;
    }

    // i-side registers. q<5: raw p_i; q>=5: 0.5*p_i (sat path). t raw always.
    const int ig = t & 31;
    const int jg = t >> 5;
    const int i0 = ibase + ig * RI;
    const int s0 = jg * 16;

    float4 pf0 = *(const float4*)(p  + i0);
    float4 pf1 = *(const float4*)(p  + i0 + 4);
    float4 tf0 = *(const float4*)(tg + i0);
    float4 tf1 = *(const float4*)(tg + i0 + 4);

    __half2 ap[RI], at[RI], accP[RI], accT;
    {
        float pv[RI] = {pf0.x, pf0.y, pf0.z, pf0.w, pf1.x, pf1.y, pf1.z, pf1.w};
        float tv[RI] = {tf0.x, tf0.y, tf0.z, tf0.w, tf1.x, tf1.y, tf1.z, tf1.w};
#pragma unroll
        for (int q = 0; q < RI; q++) {
            float scale = (q >= RI - NSAT) ? 0.5f : 1.0f;
            ap[q]   = __half2half2(__float2half_rn(scale * pv[q]));
            at[q]   = __half2half2(__float2half_rn(tv[q]));
            accP[q] = __float2half2_rn(0.0f);
        }
        accT = __float2half2_rn(0.0f);
    }
    const __half2 one2  = __float2half2_rn(1.0f);
    const __half2 mone2 = __float2half2_rn(-1.0f);
    __syncthreads();

#pragma unroll
    for (int s = 0; s < 16; s++) {
        uint2    vA = sjA[s0 + s];       // warp-uniform broadcast
        unsigned vB = sjB[s0 + s];
        __half2 np2 = *(__half2*)&vA.x;
        __half2 nt2 = *(__half2*)&vA.y;
        __half2 bp2 = *(__half2*)&vB;
#pragma unroll
        for (int q = 0; q < RI; q++) {
            __half2 td = __hadd2(at[q], nt2);       // fma
            td = __hmin2(td, one2);                 // alu
            td = __hmax2(td, mone2);                // alu
            if (q < RI - NSAT) {
                __half2 pd = __hadd2(ap[q], np2);   // fma
                pd = __hmin2(pd, one2);             // alu
                pd = __hmax2(pd, mone2);            // alu
                accP[q] = __hfma2(pd, td, accP[q]); // fma
            } else {
                __half2 pds = __hadd2_sat(ap[q], bp2); // fma: (clip+1)/2
                accP[q] = __hfma2(pds, td, accP[q]);   // fma
                accT = __hadd2(accT, td);              // fma: -td correction
            }
        }
    }

    // Per-thread combine in fp32: minmax q's add P; sat q's add 2P - T.
    float faP = 0.0f;
#pragma unroll
    for (int q = 0; q < RI; q++) {
        float2 f = __half22float2(accP[q]);
        float w = (q >= RI - NSAT) ? 2.0f : 1.0f;
        faP += w * (f.x + f.y);
    }
    {
        float2 f = __half22float2(accT);
        faP -= f.x + f.y;
    }

    // Deterministic block reduction
#pragma unroll
    for (int off = 16; off; off >>= 1)
        faP += __shfl_down_sync(0xffffffffu, faP, off);
    __shared__ float wsum[8];
    if ((t & 31) == 0) wsum[t >> 5] = faP;
    __syncthreads();

    __shared__ int s_last;
    if (t == 0) {
        float bs = 0.0f;
#pragma unroll
        for (int w = 0; w < 8; w++) bs += wsum[w];
        double wgt = (bi == bj) ? 1.0 : 2.0;   // off-diag tile covers both orientations
        g_part[b] = wgt * (double)bs;
        __threadfence();
        unsigned int done = atomicAdd(&g_done, 1u);
        s_last = (done == (unsigned int)(nblocks - 1));
    }
    __syncthreads();

    if (s_last) {
        // Last block: fixed-order double reduction over all tile partials.
        __shared__ double sd[256];
        double s = 0.0;
        for (int k = t; k < nblocks; k += 256) s += g_part[k];
        sd[t] = s;
        __syncthreads();
        for (int off = 128; off; off >>= 1) {
            if (t < off) sd[t] += sd[t + off];
            __syncthreads();
        }
        if (t == 0) {
            double denom = (double)n * (double)(n - 1);
            out[0] = (float)(1.0 - sd[0] / denom);   // 1 - full_sum/denom
            g_done = 0;                               // reset for next graph replay
        }
    }
}

extern "C" void kernel_launch(void* const* d_in, const int* in_sizes, int n_in,
                              void* d_out, int out_size) {
    const float* p = (const float*)d_in[0];
    const float* t = (const float*)d_in[1];
    int n = in_sizes[0];              // 16384, divisible by TILE

    int T  = n / TILE;
    int nb = T * (T + 1) / 2;         // 2080 lower-triangle tiles
    pair_kernel<<<nb, 256>>>(p, t, (float*)d_out, n, nb);
}